// round 2
// baseline (speedup 1.0000x reference)
#include <cuda_runtime.h>
#include <math.h>

#define M_ROWS 4096
#define HID    768
#define NANG   20
#define QDIM   1024
#define VOCAB  30522

// Scratch (no allocations allowed)
__device__ float g_ang[M_ROWS * NANG];
__device__ float g_probs[M_ROWS * QDIM];

// ---------------------------------------------------------------------------
// K1: h = gelu(x @ W + b); LN; angles = sigmoid(h @ entw + entb) * 2pi
// 8 rows per block, 256 threads. h never leaves shared memory.
// ---------------------------------------------------------------------------
__global__ __launch_bounds__(256)
void k1_dense_ln_ang(const float* __restrict__ x,
                     const float* __restrict__ W,
                     const float* __restrict__ bias,
                     const float* __restrict__ lnw,
                     const float* __restrict__ lnb,
                     const float* __restrict__ entw,
                     const float* __restrict__ entb) {
    __shared__ float sh[8 * HID];   // x rows, then reused for h rows
    const int row0 = blockIdx.x * 8;
    const int tid  = threadIdx.x;

    for (int i = tid; i < 8 * HID; i += 256)
        sh[i] = x[row0 * HID + i];
    __syncthreads();

    float acc[8][3];
#pragma unroll
    for (int r = 0; r < 8; r++)
#pragma unroll
        for (int m = 0; m < 3; m++) acc[r][m] = 0.f;

    for (int k = 0; k < HID; k++) {
        const float w0 = W[k * HID + tid];
        const float w1 = W[k * HID + tid + 256];
        const float w2 = W[k * HID + tid + 512];
#pragma unroll
        for (int r = 0; r < 8; r++) {
            const float xv = sh[r * HID + k];
            acc[r][0] = fmaf(xv, w0, acc[r][0]);
            acc[r][1] = fmaf(xv, w1, acc[r][1]);
            acc[r][2] = fmaf(xv, w2, acc[r][2]);
        }
    }
    __syncthreads();   // done reading x from shared

    // GELU, write h into shared
#pragma unroll
    for (int m = 0; m < 3; m++) {
        const int j  = tid + m * 256;
        const float bj = bias[j];
#pragma unroll
        for (int r = 0; r < 8; r++) {
            const float v = acc[r][m] + bj;
            sh[r * HID + j] = v * 0.5f * (1.0f + erff(v * 0.70710678118654752f));
        }
    }
    __syncthreads();

    // LayerNorm: warp w owns row w (8 warps, 8 rows)
    const int w = tid >> 5, lane = tid & 31;
    {
        float s = 0.f, s2 = 0.f;
        for (int k = lane; k < HID; k += 32) {
            const float v = sh[w * HID + k];
            s += v; s2 += v * v;
        }
#pragma unroll
        for (int o = 16; o; o >>= 1) {
            s  += __shfl_xor_sync(0xffffffffu, s,  o);
            s2 += __shfl_xor_sync(0xffffffffu, s2, o);
        }
        const float mean = s * (1.0f / HID);
        const float var  = s2 * (1.0f / HID) - mean * mean;
        const float inv  = rsqrtf(var + 1e-12f);
        for (int k = lane; k < HID; k += 32) {
            const float v = (sh[w * HID + k] - mean) * inv;
            sh[w * HID + k] = lnw[k] * v + lnb[k];
        }
    }
    // rows are warp-private from here on; no block sync needed

    // angles: 20 dot products of length 768 per row
    for (int o = 0; o < NANG; o++) {
        float a = 0.f;
        for (int k = lane; k < HID; k += 32)
            a = fmaf(sh[w * HID + k], entw[k * NANG + o], a);
#pragma unroll
        for (int off = 16; off; off >>= 1)
            a += __shfl_xor_sync(0xffffffffu, a, off);
        if (lane == 0) {
            const float z  = a + entb[o];
            const float sg = 1.0f / (1.0f + expf(-z));
            g_ang[(row0 + w) * NANG + o] = sg * 6.283185307179586f;
        }
    }
}

// ---------------------------------------------------------------------------
// K2: quantum circuit. One block per row, 512 threads, statevector in shared.
// RX(theta,q): b0 = c*a0 - i*s*a1 ; b1 = c*a1 - i*s*a0   (pair stride 2^(9-q))
// CNOT ring composed into ONE gather: f = p0∘p1∘...∘p9 (GF(2)-linear).
// ---------------------------------------------------------------------------
__global__ __launch_bounds__(512)
void k2_quantum() {
    __shared__ float2 st[QDIM];
    __shared__ float cb[NANG], sb[NANG];
    const int row = blockIdx.x;
    const int tid = threadIdx.x;

    if (tid < NANG) {
        const float th = g_ang[row * NANG + tid] * 0.5f;
        sincosf(th, &sb[tid], &cb[tid]);
    }
    st[tid]       = (tid == 0) ? make_float2(1.f, 0.f) : make_float2(0.f, 0.f);
    st[tid + 512] = make_float2(0.f, 0.f);
    __syncthreads();

    for (int l = 0; l < 2; l++) {
#pragma unroll
        for (int q = 0; q < 10; q++) {
            const int b = 9 - q;
            const int S = 1 << b;
            const float c = cb[l * 10 + q];
            const float s = sb[l * 10 + q];
            const int low = tid & (S - 1);
            const int i0  = ((tid >> b) << (b + 1)) | low;
            const int i1  = i0 | S;
            const float2 a0 = st[i0];
            const float2 a1 = st[i1];
            float2 b0, b1;
            b0.x = c * a0.x + s * a1.y;
            b0.y = c * a0.y - s * a1.x;
            b1.x = c * a1.x + s * a0.y;
            b1.y = c * a1.y - s * a0.x;
            st[i0] = b0;
            st[i1] = b1;
            __syncthreads();
        }
        // composed CNOT chain: new[i] = old[p0(p1(...p9(i)))]
        int j0 = tid, j1 = tid + 512;
#pragma unroll
        for (int q = 9; q >= 0; q--) {
            const int cbit = 9 - q;
            const int tbit = 9 - ((q + 1) % 10);
            j0 ^= ((j0 >> cbit) & 1) << tbit;
            j1 ^= ((j1 >> cbit) & 1) << tbit;
        }
        const float2 r0 = st[j0];
        const float2 r1 = st[j1];
        __syncthreads();
        st[tid]       = r0;
        st[tid + 512] = r1;
        __syncthreads();
    }

    const float2 v0 = st[tid];
    const float2 v1 = st[tid + 512];
    g_probs[row * QDIM + tid]       = v0.x * v0.x + v0.y * v0.y;
    g_probs[row * QDIM + tid + 512] = v1.x * v1.x + v1.y * v1.y;
}

// ---------------------------------------------------------------------------
// K3: out = probs(4096x1024) @ proj_w(1024x30522) + proj_b
// Classic SGEMM: 128x128 tile, BK=8, 256 threads, 8x8 per thread, dbl-buffered
// NOTE: VOCAB=30522 is not a multiple of 4 -> B row starts are only 8-byte
// aligned. All global B accesses use float2 (LDG.64), never float4.
// ---------------------------------------------------------------------------
__global__ __launch_bounds__(256)
void k3_proj(const float* __restrict__ Wp,
             const float* __restrict__ pb,
             float* __restrict__ out) {
    __shared__ float As[2][8][128];
    __shared__ float Bs[2][8][128];

    const int tid  = threadIdx.x;
    const int tx   = tid & 15;       // 0..15
    const int ty   = tid >> 4;       // 0..15
    const int col0 = blockIdx.x * 128;
    const int row0 = blockIdx.y * 128;
    const bool full = (col0 + 128) <= VOCAB;

    // A load mapping: one float4 per thread
    const int ar = tid >> 1;           // 0..127
    const int ak = (tid & 1) * 4;      // 0 or 4
    // B load mapping: 4 floats (2x float2) per thread
    const int bk = tid >> 5;           // 0..7
    const int bc = (tid & 31) * 4;     // 0..124

    float acc[8][8];
#pragma unroll
    for (int i = 0; i < 8; i++)
#pragma unroll
        for (int j = 0; j < 8; j++) acc[i][j] = 0.f;

    const float* Aptr = g_probs + (row0 + ar) * QDIM + ak;

    // prologue: stage 0
    {
        const float4 av = *(const float4*)(Aptr);
        As[0][ak + 0][ar] = av.x; As[0][ak + 1][ar] = av.y;
        As[0][ak + 2][ar] = av.z; As[0][ak + 3][ar] = av.w;
        if (full) {
            const float* bp = Wp + (long)bk * VOCAB + col0 + bc;   // 8B aligned
            const float2 b0 = *(const float2*)(bp);
            const float2 b1 = *(const float2*)(bp + 2);
            Bs[0][bk][bc + 0] = b0.x; Bs[0][bk][bc + 1] = b0.y;
            Bs[0][bk][bc + 2] = b1.x; Bs[0][bk][bc + 3] = b1.y;
        } else {
#pragma unroll
            for (int i = 0; i < 4; i++) {
                const int c = col0 + bc + i;
                Bs[0][bk][bc + i] = (c < VOCAB) ? Wp[(long)bk * VOCAB + c] : 0.f;
            }
        }
    }
    __syncthreads();

    int buf = 0;
    for (int kb = 0; kb < QDIM / 8; kb++) {
        float4 av;
        float  bvx[4];
        const bool more = (kb + 1) < (QDIM / 8);
        if (more) {
            av = *(const float4*)(Aptr + (kb + 1) * 8);
            const int kg = (kb + 1) * 8 + bk;
            if (full) {
                const float* bp = Wp + (long)kg * VOCAB + col0 + bc;  // 8B aligned
                const float2 b0 = *(const float2*)(bp);
                const float2 b1 = *(const float2*)(bp + 2);
                bvx[0] = b0.x; bvx[1] = b0.y; bvx[2] = b1.x; bvx[3] = b1.y;
            } else {
#pragma unroll
                for (int i = 0; i < 4; i++) {
                    const int c = col0 + bc + i;
                    bvx[i] = (c < VOCAB) ? Wp[(long)kg * VOCAB + c] : 0.f;
                }
            }
        }

#pragma unroll
        for (int k = 0; k < 8; k++) {
            float a[8], b[8];
            const float4 a0 = *(const float4*)&As[buf][k][ty * 8];
            const float4 a1 = *(const float4*)&As[buf][k][ty * 8 + 4];
            const float4 b0 = *(const float4*)&Bs[buf][k][tx * 8];
            const float4 b1 = *(const float4*)&Bs[buf][k][tx * 8 + 4];
            a[0]=a0.x;a[1]=a0.y;a[2]=a0.z;a[3]=a0.w;a[4]=a1.x;a[5]=a1.y;a[6]=a1.z;a[7]=a1.w;
            b[0]=b0.x;b[1]=b0.y;b[2]=b0.z;b[3]=b0.w;b[4]=b1.x;b[5]=b1.y;b[6]=b1.z;b[7]=b1.w;
#pragma unroll
            for (int i = 0; i < 8; i++)
#pragma unroll
                for (int j = 0; j < 8; j++)
                    acc[i][j] = fmaf(a[i], b[j], acc[i][j]);
        }

        if (more) {
            const int nb = buf ^ 1;
            As[nb][ak + 0][ar] = av.x; As[nb][ak + 1][ar] = av.y;
            As[nb][ak + 2][ar] = av.z; As[nb][ak + 3][ar] = av.w;
            Bs[nb][bk][bc + 0] = bvx[0]; Bs[nb][bk][bc + 1] = bvx[1];
            Bs[nb][bk][bc + 2] = bvx[2]; Bs[nb][bk][bc + 3] = bvx[3];
        }
        __syncthreads();
        buf ^= 1;
    }

    // epilogue
#pragma unroll
    for (int i = 0; i < 8; i++) {
        const int row = row0 + ty * 8 + i;
#pragma unroll
        for (int j = 0; j < 8; j++) {
            const int col = col0 + tx * 8 + j;
            if (col < VOCAB)
                out[(long)row * VOCAB + col] = acc[i][j] + pb[col];
        }
    }
}

// ---------------------------------------------------------------------------
extern "C" void kernel_launch(void* const* d_in, const int* in_sizes, int n_in,
                              void* d_out, int out_size) {
    const float* x    = (const float*)d_in[0];
    const float* W    = (const float*)d_in[1];
    const float* db   = (const float*)d_in[2];
    const float* lnw  = (const float*)d_in[3];
    const float* lnb  = (const float*)d_in[4];
    const float* entw = (const float*)d_in[5];
    const float* entb = (const float*)d_in[6];
    const float* pw   = (const float*)d_in[7];
    const float* pb   = (const float*)d_in[8];
    float* out = (float*)d_out;

    k1_dense_ln_ang<<<M_ROWS / 8, 256>>>(x, W, db, lnw, lnb, entw, entb);
    k2_quantum<<<M_ROWS, 512>>>();
    dim3 g3((VOCAB + 127) / 128, M_ROWS / 128);
    k3_proj<<<g3, 256>>>(pw, pb, out);
}

// round 3
// speedup vs baseline: 2.4710x; 2.4710x over previous
#include <cuda_runtime.h>
#include <math.h>
#include <stdint.h>

#define M_ROWS 4096
#define HID    768
#define NANG   20
#define QDIM   1024
#define VOCAB  30522

// Scratch (no allocations allowed)
__device__ float g_ang[M_ROWS * NANG];
__device__ float g_probs[M_ROWS * QDIM];

// ---------------------------------------------------------------------------
// K1: h = gelu(x @ W + b); LN; angles = sigmoid(h @ entw + entb) * 2pi
// ---------------------------------------------------------------------------
__global__ __launch_bounds__(256)
void k1_dense_ln_ang(const float* __restrict__ x,
                     const float* __restrict__ W,
                     const float* __restrict__ bias,
                     const float* __restrict__ lnw,
                     const float* __restrict__ lnb,
                     const float* __restrict__ entw,
                     const float* __restrict__ entb) {
    __shared__ float sh[8 * HID];
    const int row0 = blockIdx.x * 8;
    const int tid  = threadIdx.x;

    for (int i = tid; i < 8 * HID; i += 256)
        sh[i] = x[row0 * HID + i];
    __syncthreads();

    float acc[8][3];
#pragma unroll
    for (int r = 0; r < 8; r++)
#pragma unroll
        for (int m = 0; m < 3; m++) acc[r][m] = 0.f;

    for (int k = 0; k < HID; k++) {
        const float w0 = W[k * HID + tid];
        const float w1 = W[k * HID + tid + 256];
        const float w2 = W[k * HID + tid + 512];
#pragma unroll
        for (int r = 0; r < 8; r++) {
            const float xv = sh[r * HID + k];
            acc[r][0] = fmaf(xv, w0, acc[r][0]);
            acc[r][1] = fmaf(xv, w1, acc[r][1]);
            acc[r][2] = fmaf(xv, w2, acc[r][2]);
        }
    }
    __syncthreads();

#pragma unroll
    for (int m = 0; m < 3; m++) {
        const int j  = tid + m * 256;
        const float bj = bias[j];
#pragma unroll
        for (int r = 0; r < 8; r++) {
            const float v = acc[r][m] + bj;
            sh[r * HID + j] = v * 0.5f * (1.0f + erff(v * 0.70710678118654752f));
        }
    }
    __syncthreads();

    const int w = tid >> 5, lane = tid & 31;
    {
        float s = 0.f, s2 = 0.f;
        for (int k = lane; k < HID; k += 32) {
            const float v = sh[w * HID + k];
            s += v; s2 += v * v;
        }
#pragma unroll
        for (int o = 16; o; o >>= 1) {
            s  += __shfl_xor_sync(0xffffffffu, s,  o);
            s2 += __shfl_xor_sync(0xffffffffu, s2, o);
        }
        const float mean = s * (1.0f / HID);
        const float var  = s2 * (1.0f / HID) - mean * mean;
        const float inv  = rsqrtf(var + 1e-12f);
        for (int k = lane; k < HID; k += 32) {
            const float v = (sh[w * HID + k] - mean) * inv;
            sh[w * HID + k] = lnw[k] * v + lnb[k];
        }
    }

    for (int o = 0; o < NANG; o++) {
        float a = 0.f;
        for (int k = lane; k < HID; k += 32)
            a = fmaf(sh[w * HID + k], entw[k * NANG + o], a);
#pragma unroll
        for (int off = 16; off; off >>= 1)
            a += __shfl_xor_sync(0xffffffffu, a, off);
        if (lane == 0) {
            const float z  = a + entb[o];
            const float sg = 1.0f / (1.0f + expf(-z));
            g_ang[(row0 + w) * NANG + o] = sg * 6.283185307179586f;
        }
    }
}

// ---------------------------------------------------------------------------
// K2: quantum circuit. One block per row, 512 threads, statevector in shared.
// ---------------------------------------------------------------------------
__global__ __launch_bounds__(512)
void k2_quantum() {
    __shared__ float2 st[QDIM];
    __shared__ float cb[NANG], sb[NANG];
    const int row = blockIdx.x;
    const int tid = threadIdx.x;

    if (tid < NANG) {
        const float th = g_ang[row * NANG + tid] * 0.5f;
        sincosf(th, &sb[tid], &cb[tid]);
    }
    st[tid]       = (tid == 0) ? make_float2(1.f, 0.f) : make_float2(0.f, 0.f);
    st[tid + 512] = make_float2(0.f, 0.f);
    __syncthreads();

    for (int l = 0; l < 2; l++) {
#pragma unroll
        for (int q = 0; q < 10; q++) {
            const int b = 9 - q;
            const int S = 1 << b;
            const float c = cb[l * 10 + q];
            const float s = sb[l * 10 + q];
            const int low = tid & (S - 1);
            const int i0  = ((tid >> b) << (b + 1)) | low;
            const int i1  = i0 | S;
            const float2 a0 = st[i0];
            const float2 a1 = st[i1];
            float2 b0, b1;
            b0.x = c * a0.x + s * a1.y;
            b0.y = c * a0.y - s * a1.x;
            b1.x = c * a1.x + s * a0.y;
            b1.y = c * a1.y - s * a0.x;
            st[i0] = b0;
            st[i1] = b1;
            __syncthreads();
        }
        int j0 = tid, j1 = tid + 512;
#pragma unroll
        for (int q = 9; q >= 0; q--) {
            const int cbit = 9 - q;
            const int tbit = 9 - ((q + 1) % 10);
            j0 ^= ((j0 >> cbit) & 1) << tbit;
            j1 ^= ((j1 >> cbit) & 1) << tbit;
        }
        const float2 r0 = st[j0];
        const float2 r1 = st[j1];
        __syncthreads();
        st[tid]       = r0;
        st[tid + 512] = r1;
        __syncthreads();
    }

    const float2 v0 = st[tid];
    const float2 v1 = st[tid + 512];
    g_probs[row * QDIM + tid]       = v0.x * v0.x + v0.y * v0.y;
    g_probs[row * QDIM + tid + 512] = v1.x * v1.x + v1.y * v1.y;
}

// ---------------------------------------------------------------------------
// K3: out = probs(4096x1024) @ proj_w(1024x30522) + proj_b
// Tensor-core tf32 mma.sync m16n8k8, fp32 accumulate.
// CTA tile 128x128x16, 8 warps (2x4), warp tile 64x32.
// SMEM k-major with pad 8 -> conflict-free fragment loads.
// ---------------------------------------------------------------------------
#define BM 128
#define BN 128
#define BK 16
#define PAD 8

__device__ __forceinline__ uint32_t f2tf32(float f) {
    uint32_t o;
    asm("cvt.rna.tf32.f32 %0, %1;" : "=r"(o) : "f"(f));
    return o;
}

__global__ __launch_bounds__(256)
void k3_proj_tc(const float* __restrict__ Wp,
                const float* __restrict__ pb,
                float* __restrict__ out) {
    __shared__ uint32_t As[2][BK][BM + PAD];
    __shared__ uint32_t Bs[2][BK][BN + PAD];

    const int tid  = threadIdx.x;
    const int w    = tid >> 5;
    const int lane = tid & 31;
    const int g    = lane >> 2;     // group 0..7
    const int tig  = lane & 3;      // thread-in-group

    const int col0 = blockIdx.x * BN;
    const int row0 = blockIdx.y * BM;
    const bool full = (col0 + BN) <= VOCAB;

    const int warp_m = (w & 1) * 64;
    const int warp_n = (w >> 1) * 32;

    // global->smem mappings
    const int ar = tid >> 1;            // 0..127 (A row)
    const int ak = (tid & 1) * 8;       // 0 or 8 (A k-offset)
    const int bkr = tid >> 4;           // 0..15 (B k-row)
    const int bc  = (tid & 15) * 8;     // 0..120 (B col-offset)

    const float* Aptr = g_probs + (long)(row0 + ar) * QDIM + ak;
    const float* Bbase = Wp + (long)bkr * VOCAB + col0 + bc;

    float acc[4][4][4];                 // [mt][nt][c0..c3]
#pragma unroll
    for (int i = 0; i < 4; i++)
#pragma unroll
        for (int j = 0; j < 4; j++)
#pragma unroll
            for (int c = 0; c < 4; c++) acc[i][j][c] = 0.f;

    float areg[8], breg[8];

    // prologue loads (stage 0)
    {
        const float4 a0 = *(const float4*)(Aptr);
        const float4 a1 = *(const float4*)(Aptr + 4);
        areg[0]=a0.x;areg[1]=a0.y;areg[2]=a0.z;areg[3]=a0.w;
        areg[4]=a1.x;areg[5]=a1.y;areg[6]=a1.z;areg[7]=a1.w;
        if (full) {
#pragma unroll
            for (int i = 0; i < 4; i++) {
                const float2 b = *(const float2*)(Bbase + i * 2);
                breg[i*2] = b.x; breg[i*2+1] = b.y;
            }
        } else {
#pragma unroll
            for (int i = 0; i < 8; i++) {
                const int c = col0 + bc + i;
                breg[i] = (c < VOCAB) ? Bbase[i] : 0.f;
            }
        }
#pragma unroll
        for (int i = 0; i < 8; i++) As[0][ak + i][ar] = f2tf32(areg[i]);
#pragma unroll
        for (int i = 0; i < 8; i++) Bs[0][bkr][bc + i] = f2tf32(breg[i]);
    }
    __syncthreads();

    int buf = 0;
    const int KB = QDIM / BK;    // 64
    for (int kb = 0; kb < KB; kb++) {
        const bool more = (kb + 1) < KB;
        if (more) {
            const float4 a0 = *(const float4*)(Aptr + (kb + 1) * BK);
            const float4 a1 = *(const float4*)(Aptr + (kb + 1) * BK + 4);
            areg[0]=a0.x;areg[1]=a0.y;areg[2]=a0.z;areg[3]=a0.w;
            areg[4]=a1.x;areg[5]=a1.y;areg[6]=a1.z;areg[7]=a1.w;
            const float* bp = Bbase + (long)(kb + 1) * BK * VOCAB;
            if (full) {
#pragma unroll
                for (int i = 0; i < 4; i++) {
                    const float2 b = *(const float2*)(bp + i * 2);
                    breg[i*2] = b.x; breg[i*2+1] = b.y;
                }
            } else {
#pragma unroll
                for (int i = 0; i < 8; i++) {
                    const int c = col0 + bc + i;
                    breg[i] = (c < VOCAB) ? bp[i] : 0.f;
                }
            }
        }

        // compute on stage buf
#pragma unroll
        for (int ks = 0; ks < 2; ks++) {
            const int k0 = ks * 8;
            uint32_t af[4][4];
            uint32_t bf[4][2];
#pragma unroll
            for (int mt = 0; mt < 4; mt++) {
                const int m0 = warp_m + mt * 16;
                af[mt][0] = As[buf][k0 + tig    ][m0 + g    ];
                af[mt][1] = As[buf][k0 + tig    ][m0 + g + 8];
                af[mt][2] = As[buf][k0 + tig + 4][m0 + g    ];
                af[mt][3] = As[buf][k0 + tig + 4][m0 + g + 8];
            }
#pragma unroll
            for (int nt = 0; nt < 4; nt++) {
                const int n0 = warp_n + nt * 8;
                bf[nt][0] = Bs[buf][k0 + tig    ][n0 + g];
                bf[nt][1] = Bs[buf][k0 + tig + 4][n0 + g];
            }
#pragma unroll
            for (int mt = 0; mt < 4; mt++)
#pragma unroll
                for (int nt = 0; nt < 4; nt++) {
                    asm volatile(
                        "mma.sync.aligned.m16n8k8.row.col.f32.tf32.tf32.f32 "
                        "{%0,%1,%2,%3}, {%4,%5,%6,%7}, {%8,%9}, {%0,%1,%2,%3};"
                        : "+f"(acc[mt][nt][0]), "+f"(acc[mt][nt][1]),
                          "+f"(acc[mt][nt][2]), "+f"(acc[mt][nt][3])
                        : "r"(af[mt][0]), "r"(af[mt][1]),
                          "r"(af[mt][2]), "r"(af[mt][3]),
                          "r"(bf[nt][0]), "r"(bf[nt][1]));
                }
        }

        if (more) {
            const int nb = buf ^ 1;
#pragma unroll
            for (int i = 0; i < 8; i++) As[nb][ak + i][ar] = f2tf32(areg[i]);
#pragma unroll
            for (int i = 0; i < 8; i++) Bs[nb][bkr][bc + i] = f2tf32(breg[i]);
        }
        __syncthreads();
        buf ^= 1;
    }

    // epilogue: c0:(g, 2*tig) c1:(g, 2*tig+1) c2:(g+8, 2*tig) c3:(g+8, 2*tig+1)
#pragma unroll
    for (int mt = 0; mt < 4; mt++) {
#pragma unroll
        for (int nt = 0; nt < 4; nt++) {
            const int row = row0 + warp_m + mt * 16 + g;
            const int col = col0 + warp_n + nt * 8 + tig * 2;
            if (col + 1 < VOCAB) {
                const float b0 = pb[col], b1 = pb[col + 1];
                float2 v0 = make_float2(acc[mt][nt][0] + b0, acc[mt][nt][1] + b1);
                float2 v1 = make_float2(acc[mt][nt][2] + b0, acc[mt][nt][3] + b1);
                *(float2*)(out + (long)row * VOCAB + col)       = v0;
                *(float2*)(out + (long)(row + 8) * VOCAB + col) = v1;
            } else if (col < VOCAB) {
                const float b0 = pb[col];
                out[(long)row * VOCAB + col]       = acc[mt][nt][0] + b0;
                out[(long)(row + 8) * VOCAB + col] = acc[mt][nt][2] + b0;
            }
        }
    }
}

// ---------------------------------------------------------------------------
extern "C" void kernel_launch(void* const* d_in, const int* in_sizes, int n_in,
                              void* d_out, int out_size) {
    const float* x    = (const float*)d_in[0];
    const float* W    = (const float*)d_in[1];
    const float* db   = (const float*)d_in[2];
    const float* lnw  = (const float*)d_in[3];
    const float* lnb  = (const float*)d_in[4];
    const float* entw = (const float*)d_in[5];
    const float* entb = (const float*)d_in[6];
    const float* pw   = (const float*)d_in[7];
    const float* pb   = (const float*)d_in[8];
    float* out = (float*)d_out;

    k1_dense_ln_ang<<<M_ROWS / 8, 256>>>(x, W, db, lnw, lnb, entw, entb);
    k2_quantum<<<M_ROWS, 512>>>();
    dim3 g3((VOCAB + BN - 1) / BN, M_ROWS / BM);
    k3_proj_tc<<<g3, 256>>>(pw, pb, out);
}

// round 5
// speedup vs baseline: 4.3422x; 1.7573x over previous
#include <cuda_runtime.h>
#include <cuda_fp16.h>
#include <math.h>
#include <stdint.h>

#define M_ROWS 4096
#define HID    768
#define NANG   20
#define QDIM   1024
#define VOCAB  30522
#define VPAD   30592        // VOCAB rounded up to multiple of 128

// Scratch (no allocations allowed)
__device__ float  g_ang[M_ROWS * NANG];
__device__ __half g_probs16[M_ROWS * QDIM];          // 8 MB
__device__ __half g_wt[(size_t)VPAD * QDIM];         // 62.7 MB, [n][k] f16

// ---------------------------------------------------------------------------
// KT: transpose + convert proj_w (f32 [k][n]) -> g_wt (f16 [n][k]), zero pad
// ---------------------------------------------------------------------------
__global__ __launch_bounds__(256)
void kT_transpose(const float* __restrict__ Wp) {
    __shared__ float t[32][33];
    const int n0 = blockIdx.x * 32;
    const int k0 = blockIdx.y * 32;
    const int tx = threadIdx.x & 31;
    const int ty = threadIdx.x >> 5;        // 0..7
#pragma unroll
    for (int i = 0; i < 4; i++) {
        const int k = k0 + ty + i * 8;
        const int n = n0 + tx;
        t[ty + i * 8][tx] = (n < VOCAB) ? Wp[(size_t)k * VOCAB + n] : 0.f;
    }
    __syncthreads();
#pragma unroll
    for (int i = 0; i < 4; i++) {
        const int n = n0 + ty + i * 8;
        g_wt[(size_t)n * QDIM + k0 + tx] = __float2half_rn(t[tx][ty + i * 8]);
    }
}

// ---------------------------------------------------------------------------
// K1: h = gelu(x @ W + b); LN; angles = sigmoid(h @ entw + entb) * 2pi
// ---------------------------------------------------------------------------
__global__ __launch_bounds__(256)
void k1_dense_ln_ang(const float* __restrict__ x,
                     const float* __restrict__ W,
                     const float* __restrict__ bias,
                     const float* __restrict__ lnw,
                     const float* __restrict__ lnb,
                     const float* __restrict__ entw,
                     const float* __restrict__ entb) {
    __shared__ float sh[8 * HID];
    const int row0 = blockIdx.x * 8;
    const int tid  = threadIdx.x;

    for (int i = tid; i < 8 * HID; i += 256)
        sh[i] = x[row0 * HID + i];
    __syncthreads();

    float acc[8][3];
#pragma unroll
    for (int r = 0; r < 8; r++)
#pragma unroll
        for (int m = 0; m < 3; m++) acc[r][m] = 0.f;

    for (int k = 0; k < HID; k++) {
        const float w0 = W[k * HID + tid];
        const float w1 = W[k * HID + tid + 256];
        const float w2 = W[k * HID + tid + 512];
#pragma unroll
        for (int r = 0; r < 8; r++) {
            const float xv = sh[r * HID + k];
            acc[r][0] = fmaf(xv, w0, acc[r][0]);
            acc[r][1] = fmaf(xv, w1, acc[r][1]);
            acc[r][2] = fmaf(xv, w2, acc[r][2]);
        }
    }
    __syncthreads();

#pragma unroll
    for (int m = 0; m < 3; m++) {
        const int j  = tid + m * 256;
        const float bj = bias[j];
#pragma unroll
        for (int r = 0; r < 8; r++) {
            const float v = acc[r][m] + bj;
            sh[r * HID + j] = v * 0.5f * (1.0f + erff(v * 0.70710678118654752f));
        }
    }
    __syncthreads();

    const int w = tid >> 5, lane = tid & 31;
    {
        float s = 0.f, s2 = 0.f;
        for (int k = lane; k < HID; k += 32) {
            const float v = sh[w * HID + k];
            s += v; s2 += v * v;
        }
#pragma unroll
        for (int o = 16; o; o >>= 1) {
            s  += __shfl_xor_sync(0xffffffffu, s,  o);
            s2 += __shfl_xor_sync(0xffffffffu, s2, o);
        }
        const float mean = s * (1.0f / HID);
        const float var  = s2 * (1.0f / HID) - mean * mean;
        const float inv  = rsqrtf(var + 1e-12f);
        for (int k = lane; k < HID; k += 32) {
            const float v = (sh[w * HID + k] - mean) * inv;
            sh[w * HID + k] = lnw[k] * v + lnb[k];
        }
    }

    for (int o = 0; o < NANG; o++) {
        float a = 0.f;
        for (int k = lane; k < HID; k += 32)
            a = fmaf(sh[w * HID + k], entw[k * NANG + o], a);
#pragma unroll
        for (int off = 16; off; off >>= 1)
            a += __shfl_xor_sync(0xffffffffu, a, off);
        if (lane == 0) {
            const float z  = a + entb[o];
            const float sg = 1.0f / (1.0f + expf(-z));
            g_ang[(row0 + w) * NANG + o] = sg * 6.283185307179586f;
        }
    }
}

// ---------------------------------------------------------------------------
// K2: quantum circuit. One block per row, 512 threads, statevector in shared.
// Writes probabilities directly as f16.
// ---------------------------------------------------------------------------
__global__ __launch_bounds__(512)
void k2_quantum() {
    __shared__ float2 st[QDIM];
    __shared__ float cb[NANG], sb[NANG];
    const int row = blockIdx.x;
    const int tid = threadIdx.x;

    if (tid < NANG) {
        const float th = g_ang[row * NANG + tid] * 0.5f;
        sincosf(th, &sb[tid], &cb[tid]);
    }
    st[tid]       = (tid == 0) ? make_float2(1.f, 0.f) : make_float2(0.f, 0.f);
    st[tid + 512] = make_float2(0.f, 0.f);
    __syncthreads();

    for (int l = 0; l < 2; l++) {
#pragma unroll
        for (int q = 0; q < 10; q++) {
            const int b = 9 - q;
            const int S = 1 << b;
            const float c = cb[l * 10 + q];
            const float s = sb[l * 10 + q];
            const int low = tid & (S - 1);
            const int i0  = ((tid >> b) << (b + 1)) | low;
            const int i1  = i0 | S;
            const float2 a0 = st[i0];
            const float2 a1 = st[i1];
            float2 b0, b1;
            b0.x = c * a0.x + s * a1.y;
            b0.y = c * a0.y - s * a1.x;
            b1.x = c * a1.x + s * a0.y;
            b1.y = c * a1.y - s * a0.x;
            st[i0] = b0;
            st[i1] = b1;
            __syncthreads();
        }
        int j0 = tid, j1 = tid + 512;
#pragma unroll
        for (int q = 9; q >= 0; q--) {
            const int cbit = 9 - q;
            const int tbit = 9 - ((q + 1) % 10);
            j0 ^= ((j0 >> cbit) & 1) << tbit;
            j1 ^= ((j1 >> cbit) & 1) << tbit;
        }
        const float2 r0 = st[j0];
        const float2 r1 = st[j1];
        __syncthreads();
        st[tid]       = r0;
        st[tid + 512] = r1;
        __syncthreads();
    }

    const float2 v0 = st[tid];
    const float2 v1 = st[tid + 512];
    g_probs16[row * QDIM + tid]       = __float2half_rn(v0.x * v0.x + v0.y * v0.y);
    g_probs16[row * QDIM + tid + 512] = __float2half_rn(v1.x * v1.x + v1.y * v1.y);
}

// ---------------------------------------------------------------------------
// K3: out = probs(4096x1024) @ g_wt^T + proj_b   (both operands f16, acc f32)
// mma.sync m16n8k16. CTA 128x128x32, 8 warps (2x4), warp tile 64x32.
// SMEM m-/n-major, stride 40 halves -> conflict-free half2 fragment loads.
// ---------------------------------------------------------------------------
#define BM 128
#define BN 128
#define BK 32
#define LDST 40    // smem row stride in halves

__global__ __launch_bounds__(256)
void k3_proj_f16(const float* __restrict__ pb,
                 float* __restrict__ out) {
    __shared__ __half As[2][BM][LDST];
    __shared__ __half Bs[2][BN][LDST];

    const int tid  = threadIdx.x;
    const int w    = tid >> 5;
    const int lane = tid & 31;
    const int g    = lane >> 2;     // 0..7
    const int tig  = lane & 3;      // 0..3

    const int col0 = blockIdx.x * BN;
    const int row0 = blockIdx.y * BM;

    const int warp_m = (w & 1) * 64;
    const int warp_n = (w >> 1) * 32;

    // global->smem mapping: thread loads 16 halves (2 x uint4) of one row
    const int ar = tid >> 1;            // 0..127
    const int ak = (tid & 1) * 16;      // 0 or 16 (halves)

    const __half* Ag = g_probs16 + (size_t)(row0 + ar) * QDIM + ak;
    const __half* Bg = g_wt      + (size_t)(col0 + ar) * QDIM + ak;

    float acc[4][4][4];
#pragma unroll
    for (int i = 0; i < 4; i++)
#pragma unroll
        for (int j = 0; j < 4; j++)
#pragma unroll
            for (int c = 0; c < 4; c++) acc[i][j][c] = 0.f;

    uint4 a0p, a1p, b0p, b1p;

    // prologue: stage 0
    a0p = *(const uint4*)(Ag);
    a1p = *(const uint4*)(Ag + 8);
    b0p = *(const uint4*)(Bg);
    b1p = *(const uint4*)(Bg + 8);
    *(uint4*)&As[0][ar][ak]     = a0p;
    *(uint4*)&As[0][ar][ak + 8] = a1p;
    *(uint4*)&Bs[0][ar][ak]     = b0p;
    *(uint4*)&Bs[0][ar][ak + 8] = b1p;
    __syncthreads();

    int buf = 0;
    const int KB = QDIM / BK;    // 32
    for (int kb = 0; kb < KB; kb++) {
        const bool more = (kb + 1) < KB;
        if (more) {
            a0p = *(const uint4*)(Ag + (kb + 1) * BK);
            a1p = *(const uint4*)(Ag + (kb + 1) * BK + 8);
            b0p = *(const uint4*)(Bg + (kb + 1) * BK);
            b1p = *(const uint4*)(Bg + (kb + 1) * BK + 8);
        }

#pragma unroll
        for (int ks = 0; ks < 2; ks++) {
            const int k0 = ks * 16;
            uint32_t af[4][4];
            uint32_t bf[4][2];
#pragma unroll
            for (int mt = 0; mt < 4; mt++) {
                const int m0 = warp_m + mt * 16;
                af[mt][0] = *(const uint32_t*)&As[buf][m0 + g    ][k0 + 2 * tig];
                af[mt][1] = *(const uint32_t*)&As[buf][m0 + g + 8][k0 + 2 * tig];
                af[mt][2] = *(const uint32_t*)&As[buf][m0 + g    ][k0 + 8 + 2 * tig];
                af[mt][3] = *(const uint32_t*)&As[buf][m0 + g + 8][k0 + 8 + 2 * tig];
            }
#pragma unroll
            for (int nt = 0; nt < 4; nt++) {
                const int n0 = warp_n + nt * 8;
                bf[nt][0] = *(const uint32_t*)&Bs[buf][n0 + g][k0 + 2 * tig];
                bf[nt][1] = *(const uint32_t*)&Bs[buf][n0 + g][k0 + 8 + 2 * tig];
            }
#pragma unroll
            for (int mt = 0; mt < 4; mt++)
#pragma unroll
                for (int nt = 0; nt < 4; nt++) {
                    asm volatile(
                        "mma.sync.aligned.m16n8k16.row.col.f32.f16.f16.f32 "
                        "{%0,%1,%2,%3}, {%4,%5,%6,%7}, {%8,%9}, {%0,%1,%2,%3};"
                        : "+f"(acc[mt][nt][0]), "+f"(acc[mt][nt][1]),
                          "+f"(acc[mt][nt][2]), "+f"(acc[mt][nt][3])
                        : "r"(af[mt][0]), "r"(af[mt][1]),
                          "r"(af[mt][2]), "r"(af[mt][3]),
                          "r"(bf[nt][0]), "r"(bf[nt][1]));
                }
        }

        if (more) {
            const int nb = buf ^ 1;
            *(uint4*)&As[nb][ar][ak]     = a0p;
            *(uint4*)&As[nb][ar][ak + 8] = a1p;
            *(uint4*)&Bs[nb][ar][ak]     = b0p;
            *(uint4*)&Bs[nb][ar][ak + 8] = b1p;
        }
        __syncthreads();
        buf ^= 1;
    }

    // epilogue: c0:(g, 2tig) c1:(g, 2tig+1) c2:(g+8, 2tig) c3:(g+8, 2tig+1)
#pragma unroll
    for (int mt = 0; mt < 4; mt++) {
#pragma unroll
        for (int nt = 0; nt < 4; nt++) {
            const int row = row0 + warp_m + mt * 16 + g;
            const int col = col0 + warp_n + nt * 8 + tig * 2;
            if (col < VOCAB) {   // VOCAB even -> pair never straddles
                const float b0 = pb[col], b1 = pb[col + 1];
                float2 v0 = make_float2(acc[mt][nt][0] + b0, acc[mt][nt][1] + b1);
                float2 v1 = make_float2(acc[mt][nt][2] + b0, acc[mt][nt][3] + b1);
                *(float2*)(out + (size_t)row * VOCAB + col)       = v0;
                *(float2*)(out + (size_t)(row + 8) * VOCAB + col) = v1;
            }
        }
    }
}

// ---------------------------------------------------------------------------
extern "C" void kernel_launch(void* const* d_in, const int* in_sizes, int n_in,
                              void* d_out, int out_size) {
    const float* x    = (const float*)d_in[0];
    const float* W    = (const float*)d_in[1];
    const float* db   = (const float*)d_in[2];
    const float* lnw  = (const float*)d_in[3];
    const float* lnb  = (const float*)d_in[4];
    const float* entw = (const float*)d_in[5];
    const float* entb = (const float*)d_in[6];
    const float* pw   = (const float*)d_in[7];
    const float* pb   = (const float*)d_in[8];
    float* out = (float*)d_out;

    dim3 gT(VPAD / 32, QDIM / 32);
    kT_transpose<<<gT, 256>>>(pw);
    k1_dense_ln_ang<<<M_ROWS / 8, 256>>>(x, W, db, lnw, lnb, entw, entb);
    k2_quantum<<<M_ROWS, 512>>>();
    dim3 g3(VPAD / BN, M_ROWS / BM);
    k3_proj_f16<<<g3, 256>>>(pb, out);
}

// round 6
// speedup vs baseline: 5.3956x; 1.2426x over previous
#include <cuda_runtime.h>
#include <cuda_fp16.h>
#include <math.h>
#include <stdint.h>

#define M_ROWS 4096
#define HID    768
#define NANG   20
#define QDIM   1024
#define VOCAB  30522
#define VPAD   30720        // VOCAB rounded up to multiple of 256

// Scratch (no allocations allowed)
__device__ float  g_ang[M_ROWS * NANG];
__device__ __half g_probs16[M_ROWS * QDIM];          // 8 MB
__device__ __half g_wt[(size_t)VPAD * QDIM];         // 63 MB, [n][k] f16

// ---------------------------------------------------------------------------
// KT: transpose + convert proj_w (f32 [k][n]) -> g_wt (f16 [n][k]), zero pad
// ---------------------------------------------------------------------------
__global__ __launch_bounds__(256)
void kT_transpose(const float* __restrict__ Wp) {
    __shared__ float t[32][33];
    const int n0 = blockIdx.x * 32;
    const int k0 = blockIdx.y * 32;
    const int tx = threadIdx.x & 31;
    const int ty = threadIdx.x >> 5;        // 0..7
#pragma unroll
    for (int i = 0; i < 4; i++) {
        const int k = k0 + ty + i * 8;
        const int n = n0 + tx;
        t[ty + i * 8][tx] = (n < VOCAB) ? Wp[(size_t)k * VOCAB + n] : 0.f;
    }
    __syncthreads();
#pragma unroll
    for (int i = 0; i < 4; i++) {
        const int n = n0 + ty + i * 8;
        g_wt[(size_t)n * QDIM + k0 + tx] = __float2half_rn(t[tx][ty + i * 8]);
    }
}

// ---------------------------------------------------------------------------
// K1: h = gelu(x @ W + b); LN; angles = sigmoid(h @ entw + entb) * 2pi
// ---------------------------------------------------------------------------
__global__ __launch_bounds__(256)
void k1_dense_ln_ang(const float* __restrict__ x,
                     const float* __restrict__ W,
                     const float* __restrict__ bias,
                     const float* __restrict__ lnw,
                     const float* __restrict__ lnb,
                     const float* __restrict__ entw,
                     const float* __restrict__ entb) {
    __shared__ float sh[8 * HID];
    const int row0 = blockIdx.x * 8;
    const int tid  = threadIdx.x;

    for (int i = tid; i < 8 * HID; i += 256)
        sh[i] = x[row0 * HID + i];
    __syncthreads();

    float acc[8][3];
#pragma unroll
    for (int r = 0; r < 8; r++)
#pragma unroll
        for (int m = 0; m < 3; m++) acc[r][m] = 0.f;

    for (int k = 0; k < HID; k++) {
        const float w0 = W[k * HID + tid];
        const float w1 = W[k * HID + tid + 256];
        const float w2 = W[k * HID + tid + 512];
#pragma unroll
        for (int r = 0; r < 8; r++) {
            const float xv = sh[r * HID + k];
            acc[r][0] = fmaf(xv, w0, acc[r][0]);
            acc[r][1] = fmaf(xv, w1, acc[r][1]);
            acc[r][2] = fmaf(xv, w2, acc[r][2]);
        }
    }
    __syncthreads();

#pragma unroll
    for (int m = 0; m < 3; m++) {
        const int j  = tid + m * 256;
        const float bj = bias[j];
#pragma unroll
        for (int r = 0; r < 8; r++) {
            const float v = acc[r][m] + bj;
            sh[r * HID + j] = v * 0.5f * (1.0f + erff(v * 0.70710678118654752f));
        }
    }
    __syncthreads();

    const int w = tid >> 5, lane = tid & 31;
    {
        float s = 0.f, s2 = 0.f;
        for (int k = lane; k < HID; k += 32) {
            const float v = sh[w * HID + k];
            s += v; s2 += v * v;
        }
#pragma unroll
        for (int o = 16; o; o >>= 1) {
            s  += __shfl_xor_sync(0xffffffffu, s,  o);
            s2 += __shfl_xor_sync(0xffffffffu, s2, o);
        }
        const float mean = s * (1.0f / HID);
        const float var  = s2 * (1.0f / HID) - mean * mean;
        const float inv  = rsqrtf(var + 1e-12f);
        for (int k = lane; k < HID; k += 32) {
            const float v = (sh[w * HID + k] - mean) * inv;
            sh[w * HID + k] = lnw[k] * v + lnb[k];
        }
    }

    for (int o = 0; o < NANG; o++) {
        float a = 0.f;
        for (int k = lane; k < HID; k += 32)
            a = fmaf(sh[w * HID + k], entw[k * NANG + o], a);
#pragma unroll
        for (int off = 16; off; off >>= 1)
            a += __shfl_xor_sync(0xffffffffu, a, off);
        if (lane == 0) {
            const float z  = a + entb[o];
            const float sg = 1.0f / (1.0f + expf(-z));
            g_ang[(row0 + w) * NANG + o] = sg * 6.283185307179586f;
        }
    }
}

// ---------------------------------------------------------------------------
// K2: quantum circuit. One block per row, 512 threads, statevector in shared.
// ---------------------------------------------------------------------------
__global__ __launch_bounds__(512)
void k2_quantum() {
    __shared__ float2 st[QDIM];
    __shared__ float cb[NANG], sb[NANG];
    const int row = blockIdx.x;
    const int tid = threadIdx.x;

    if (tid < NANG) {
        const float th = g_ang[row * NANG + tid] * 0.5f;
        sincosf(th, &sb[tid], &cb[tid]);
    }
    st[tid]       = (tid == 0) ? make_float2(1.f, 0.f) : make_float2(0.f, 0.f);
    st[tid + 512] = make_float2(0.f, 0.f);
    __syncthreads();

    for (int l = 0; l < 2; l++) {
#pragma unroll
        for (int q = 0; q < 10; q++) {
            const int b = 9 - q;
            const int S = 1 << b;
            const float c = cb[l * 10 + q];
            const float s = sb[l * 10 + q];
            const int low = tid & (S - 1);
            const int i0  = ((tid >> b) << (b + 1)) | low;
            const int i1  = i0 | S;
            const float2 a0 = st[i0];
            const float2 a1 = st[i1];
            float2 b0, b1;
            b0.x = c * a0.x + s * a1.y;
            b0.y = c * a0.y - s * a1.x;
            b1.x = c * a1.x + s * a0.y;
            b1.y = c * a1.y - s * a0.x;
            st[i0] = b0;
            st[i1] = b1;
            __syncthreads();
        }
        int j0 = tid, j1 = tid + 512;
#pragma unroll
        for (int q = 9; q >= 0; q--) {
            const int cbit = 9 - q;
            const int tbit = 9 - ((q + 1) % 10);
            j0 ^= ((j0 >> cbit) & 1) << tbit;
            j1 ^= ((j1 >> cbit) & 1) << tbit;
        }
        const float2 r0 = st[j0];
        const float2 r1 = st[j1];
        __syncthreads();
        st[tid]       = r0;
        st[tid + 512] = r1;
        __syncthreads();
    }

    const float2 v0 = st[tid];
    const float2 v1 = st[tid + 512];
    g_probs16[row * QDIM + tid]       = __float2half_rn(v0.x * v0.x + v0.y * v0.y);
    g_probs16[row * QDIM + tid + 512] = __float2half_rn(v1.x * v1.x + v1.y * v1.y);
}

// ---------------------------------------------------------------------------
// K3 v2: out = probs(4096x1024) @ g_wt^T + proj_b   (f16 x f16 -> f32)
// CTA 128x256x32, 8 warps (2x4), warp tile 64x64.
// 4-stage cp.async pipeline, ldmatrix.x4 fragment loads, XOR-swizzled smem.
// SMEM layout: two 32-half rows folded per 128B line; 16B chunk c ^= (line&7).
// ---------------------------------------------------------------------------
#define BM 128
#define BN 256
#define BK 32            // halves
#define STAGES 4
#define A_STG 8192       // 128*32*2 bytes
#define B_STG 16384      // 256*32*2 bytes
#define B_BASE (STAGES * A_STG)
#define K3_SMEM (STAGES * (A_STG + B_STG))   // 96 KB

__device__ __forceinline__ uint32_t smem_u32(const void* p) {
    uint32_t a;
    asm("{ .reg .u64 t; cvta.to.shared.u64 t, %1; cvt.u32.u64 %0, t; }"
        : "=r"(a) : "l"(p));
    return a;
}
__device__ __forceinline__ void cp16(uint32_t saddr, const void* gptr) {
    asm volatile("cp.async.cg.shared.global [%0], [%1], 16;"
                 :: "r"(saddr), "l"(gptr));
}
// swizzled byte offset within a tile for (row r, 16B-chunk kc), rows folded 2/line
__device__ __forceinline__ uint32_t swz(int r, int kc) {
    const int line = r >> 1;
    const int c    = ((r & 1) << 2) + kc;
    return (uint32_t)(line * 128 + ((c ^ (line & 7)) << 4));
}

__global__ __launch_bounds__(256)
void k3_proj_f16v2(const float* __restrict__ pb,
                   float* __restrict__ out) {
    extern __shared__ char smem[];
    const uint32_t sA = smem_u32(smem);
    const uint32_t sB = sA + B_BASE;

    const int tid  = threadIdx.x;
    const int w    = tid >> 5;
    const int lane = tid & 31;
    const int g    = lane >> 2;
    const int tig  = lane & 3;

    const int row0 = blockIdx.x * BM;      // 32 row tiles (fast dim)
    const int col0 = blockIdx.y * BN;      // 120 col tiles

    const int warp_m = (w & 1) * 64;
    const int warp_n = (w >> 1) * 64;

    // ---- producer mappings: A 512 chunks (2/thread), B 1024 chunks (4/thread)
    const __half* Agbase = g_probs16 + (size_t)row0 * QDIM;
    const __half* Bgbase = g_wt      + (size_t)col0 * QDIM;

    // ---- consumer ldmatrix base addresses (stage 0, ks 0)
    const int l16 = lane & 15;
    const int khf = lane >> 4;
    uint32_t aLM, bLM;
    {
        const int rr = warp_m + l16;
        aLM = sA + swz(rr, khf);
        const int rn = warp_n + l16;
        bLM = sB + swz(rn, khf);
    }

    float acc[4][8][4];
#pragma unroll
    for (int i = 0; i < 4; i++)
#pragma unroll
        for (int j = 0; j < 8; j++)
#pragma unroll
            for (int c = 0; c < 4; c++) acc[i][j][c] = 0.f;

    const int KB = QDIM / BK;   // 32

    // ---- prologue: fill stages 0..STAGES-2
#pragma unroll
    for (int s = 0; s < STAGES - 1; s++) {
        const int k0 = s * BK;
#pragma unroll
        for (int j = 0; j < 2; j++) {
            const int i = tid + j * 256;
            const int r = i >> 2, kc = i & 3;
            cp16(sA + s * A_STG + swz(r, kc),
                 Agbase + (size_t)r * QDIM + k0 + kc * 8);
        }
#pragma unroll
        for (int j = 0; j < 4; j++) {
            const int i = tid + j * 256;
            const int r = i >> 2, kc = i & 3;
            cp16(sB + s * B_STG + swz(r, kc),
                 Bgbase + (size_t)r * QDIM + k0 + kc * 8);
        }
        asm volatile("cp.async.commit_group;");
    }

    for (int kb = 0; kb < KB; kb++) {
        asm volatile("cp.async.wait_group %0;" :: "n"(STAGES - 2));
        __syncthreads();

        // issue loads for k-block kb+STAGES-1 into stage (kb+STAGES-1)%STAGES
        {
            const int kn = kb + STAGES - 1;
            if (kn < KB) {
                const int s  = kn & (STAGES - 1);
                const int k0 = kn * BK;
#pragma unroll
                for (int j = 0; j < 2; j++) {
                    const int i = tid + j * 256;
                    const int r = i >> 2, kc = i & 3;
                    cp16(sA + s * A_STG + swz(r, kc),
                         Agbase + (size_t)r * QDIM + k0 + kc * 8);
                }
#pragma unroll
                for (int j = 0; j < 4; j++) {
                    const int i = tid + j * 256;
                    const int r = i >> 2, kc = i & 3;
                    cp16(sB + s * B_STG + swz(r, kc),
                         Bgbase + (size_t)r * QDIM + k0 + kc * 8);
                }
            }
            asm volatile("cp.async.commit_group;");
        }

        // compute on stage kb%STAGES
        const int s = kb & (STAGES - 1);
        const uint32_t aS = aLM + s * A_STG;
        const uint32_t bS = bLM + s * B_STG;
#pragma unroll
        for (int ks = 0; ks < 2; ks++) {
            const uint32_t kx = ks * 32;    // chunk c bit1 toggle
            uint32_t af[4][4];
#pragma unroll
            for (int mt = 0; mt < 4; mt++) {
                asm volatile(
                    "ldmatrix.sync.aligned.m8n8.x4.shared.b16 {%0,%1,%2,%3}, [%4];"
                    : "=r"(af[mt][0]), "=r"(af[mt][1]),
                      "=r"(af[mt][2]), "=r"(af[mt][3])
                    : "r"((aS + mt * 1024) ^ kx));
            }
            uint32_t bf[8][2];
#pragma unroll
            for (int ntp = 0; ntp < 4; ntp++) {
                uint32_t r0, r1, r2, r3;
                asm volatile(
                    "ldmatrix.sync.aligned.m8n8.x4.shared.b16 {%0,%1,%2,%3}, [%4];"
                    : "=r"(r0), "=r"(r1), "=r"(r2), "=r"(r3)
                    : "r"((bS + ntp * 1024) ^ kx));
                bf[2*ntp][0]   = r0; bf[2*ntp][1]   = r2;
                bf[2*ntp+1][0] = r1; bf[2*ntp+1][1] = r3;
            }
#pragma unroll
            for (int mt = 0; mt < 4; mt++)
#pragma unroll
                for (int nt = 0; nt < 8; nt++) {
                    asm volatile(
                        "mma.sync.aligned.m16n8k16.row.col.f32.f16.f16.f32 "
                        "{%0,%1,%2,%3}, {%4,%5,%6,%7}, {%8,%9}, {%0,%1,%2,%3};"
                        : "+f"(acc[mt][nt][0]), "+f"(acc[mt][nt][1]),
                          "+f"(acc[mt][nt][2]), "+f"(acc[mt][nt][3])
                        : "r"(af[mt][0]), "r"(af[mt][1]),
                          "r"(af[mt][2]), "r"(af[mt][3]),
                          "r"(bf[nt][0]), "r"(bf[nt][1]));
                }
        }
    }

    // ---- epilogue ----
#pragma unroll
    for (int mt = 0; mt < 4; mt++) {
#pragma unroll
        for (int nt = 0; nt < 8; nt++) {
            const int row = row0 + warp_m + mt * 16 + g;
            const int col = col0 + warp_n + nt * 8 + tig * 2;
            if (col < VOCAB) {   // VOCAB even -> pair never straddles
                const float b0 = pb[col], b1 = pb[col + 1];
                float2 v0 = make_float2(acc[mt][nt][0] + b0, acc[mt][nt][1] + b1);
                float2 v1 = make_float2(acc[mt][nt][2] + b0, acc[mt][nt][3] + b1);
                __stcs((float2*)(out + (size_t)row * VOCAB + col), v0);
                __stcs((float2*)(out + (size_t)(row + 8) * VOCAB + col), v1);
            }
        }
    }
}

// ---------------------------------------------------------------------------
extern "C" void kernel_launch(void* const* d_in, const int* in_sizes, int n_in,
                              void* d_out, int out_size) {
    const float* x    = (const float*)d_in[0];
    const float* W    = (const float*)d_in[1];
    const float* db   = (const float*)d_in[2];
    const float* lnw  = (const float*)d_in[3];
    const float* lnb  = (const float*)d_in[4];
    const float* entw = (const float*)d_in[5];
    const float* entb = (const float*)d_in[6];
    const float* pw   = (const float*)d_in[7];
    const float* pb   = (const float*)d_in[8];
    float* out = (float*)d_out;

    dim3 gT(VPAD / 32, QDIM / 32);
    kT_transpose<<<gT, 256>>>(pw);
    k1_dense_ln_ang<<<M_ROWS / 8, 256>>>(x, W, db, lnw, lnb, entw, entb);
    k2_quantum<<<M_ROWS, 512>>>();

    cudaFuncSetAttribute(k3_proj_f16v2,
                         cudaFuncAttributeMaxDynamicSharedMemorySize, K3_SMEM);
    dim3 g3(M_ROWS / BM, VPAD / BN);    // (32, 120), row tiles fastest
    k3_proj_f16v2<<<g3, 256, K3_SMEM>>>(pb, out);
}

// round 7
// speedup vs baseline: 6.1320x; 1.1365x over previous
#include <cuda_runtime.h>
#include <cuda_fp16.h>
#include <math.h>
#include <stdint.h>

#define M_ROWS 4096
#define HID    768
#define NANG   20
#define QDIM   1024
#define VOCAB  30522
#define VPAD   30592        // VOCAB rounded up to multiple of 128

// Scratch (no allocations allowed)
__device__ float  g_ang[M_ROWS * NANG];
__device__ __half g_probs16[M_ROWS * QDIM];          // 8 MB
__device__ __half g_wt[(size_t)VPAD * QDIM];         // 62.7 MB, [n][k] f16

// ---------------------------------------------------------------------------
// KT: transpose + convert proj_w (f32 [k][n]) -> g_wt (f16 [n][k]), zero pad
// ---------------------------------------------------------------------------
__global__ __launch_bounds__(256)
void kT_transpose(const float* __restrict__ Wp) {
    __shared__ float t[32][33];
    const int n0 = blockIdx.x * 32;
    const int k0 = blockIdx.y * 32;
    const int tx = threadIdx.x & 31;
    const int ty = threadIdx.x >> 5;        // 0..7
#pragma unroll
    for (int i = 0; i < 4; i++) {
        const int k = k0 + ty + i * 8;
        const int n = n0 + tx;
        t[ty + i * 8][tx] = (n < VOCAB) ? Wp[(size_t)k * VOCAB + n] : 0.f;
    }
    __syncthreads();
#pragma unroll
    for (int i = 0; i < 4; i++) {
        const int n = n0 + ty + i * 8;
        g_wt[(size_t)n * QDIM + k0 + tx] = __float2half_rn(t[tx][ty + i * 8]);
    }
}

// ---------------------------------------------------------------------------
// K1: h = gelu(x @ W + b); LN; angles = sigmoid(h @ entw + entb) * 2pi
// ---------------------------------------------------------------------------
__global__ __launch_bounds__(256)
void k1_dense_ln_ang(const float* __restrict__ x,
                     const float* __restrict__ W,
                     const float* __restrict__ bias,
                     const float* __restrict__ lnw,
                     const float* __restrict__ lnb,
                     const float* __restrict__ entw,
                     const float* __restrict__ entb) {
    __shared__ float sh[8 * HID];
    const int row0 = blockIdx.x * 8;
    const int tid  = threadIdx.x;

    for (int i = tid; i < 8 * HID; i += 256)
        sh[i] = x[row0 * HID + i];
    __syncthreads();

    float acc[8][3];
#pragma unroll
    for (int r = 0; r < 8; r++)
#pragma unroll
        for (int m = 0; m < 3; m++) acc[r][m] = 0.f;

    for (int k = 0; k < HID; k++) {
        const float w0 = W[k * HID + tid];
        const float w1 = W[k * HID + tid + 256];
        const float w2 = W[k * HID + tid + 512];
#pragma unroll
        for (int r = 0; r < 8; r++) {
            const float xv = sh[r * HID + k];
            acc[r][0] = fmaf(xv, w0, acc[r][0]);
            acc[r][1] = fmaf(xv, w1, acc[r][1]);
            acc[r][2] = fmaf(xv, w2, acc[r][2]);
        }
    }
    __syncthreads();

#pragma unroll
    for (int m = 0; m < 3; m++) {
        const int j  = tid + m * 256;
        const float bj = bias[j];
#pragma unroll
        for (int r = 0; r < 8; r++) {
            const float v = acc[r][m] + bj;
            sh[r * HID + j] = v * 0.5f * (1.0f + erff(v * 0.70710678118654752f));
        }
    }
    __syncthreads();

    const int w = tid >> 5, lane = tid & 31;
    {
        float s = 0.f, s2 = 0.f;
        for (int k = lane; k < HID; k += 32) {
            const float v = sh[w * HID + k];
            s += v; s2 += v * v;
        }
#pragma unroll
        for (int o = 16; o; o >>= 1) {
            s  += __shfl_xor_sync(0xffffffffu, s,  o);
            s2 += __shfl_xor_sync(0xffffffffu, s2, o);
        }
        const float mean = s * (1.0f / HID);
        const float var  = s2 * (1.0f / HID) - mean * mean;
        const float inv  = rsqrtf(var + 1e-12f);
        for (int k = lane; k < HID; k += 32) {
            const float v = (sh[w * HID + k] - mean) * inv;
            sh[w * HID + k] = lnw[k] * v + lnb[k];
        }
    }

    for (int o = 0; o < NANG; o++) {
        float a = 0.f;
        for (int k = lane; k < HID; k += 32)
            a = fmaf(sh[w * HID + k], entw[k * NANG + o], a);
#pragma unroll
        for (int off = 16; off; off >>= 1)
            a += __shfl_xor_sync(0xffffffffu, a, off);
        if (lane == 0) {
            const float z  = a + entb[o];
            const float sg = 1.0f / (1.0f + expf(-z));
            g_ang[(row0 + w) * NANG + o] = sg * 6.283185307179586f;
        }
    }
}

// ---------------------------------------------------------------------------
// K2: quantum circuit. One block per row, 512 threads, statevector in shared.
// ---------------------------------------------------------------------------
__global__ __launch_bounds__(512)
void k2_quantum() {
    __shared__ float2 st[QDIM];
    __shared__ float cb[NANG], sb[NANG];
    const int row = blockIdx.x;
    const int tid = threadIdx.x;

    if (tid < NANG) {
        const float th = g_ang[row * NANG + tid] * 0.5f;
        sincosf(th, &sb[tid], &cb[tid]);
    }
    st[tid]       = (tid == 0) ? make_float2(1.f, 0.f) : make_float2(0.f, 0.f);
    st[tid + 512] = make_float2(0.f, 0.f);
    __syncthreads();

    for (int l = 0; l < 2; l++) {
#pragma unroll
        for (int q = 0; q < 10; q++) {
            const int b = 9 - q;
            const int S = 1 << b;
            const float c = cb[l * 10 + q];
            const float s = sb[l * 10 + q];
            const int low = tid & (S - 1);
            const int i0  = ((tid >> b) << (b + 1)) | low;
            const int i1  = i0 | S;
            const float2 a0 = st[i0];
            const float2 a1 = st[i1];
            float2 b0, b1;
            b0.x = c * a0.x + s * a1.y;
            b0.y = c * a0.y - s * a1.x;
            b1.x = c * a1.x + s * a0.y;
            b1.y = c * a1.y - s * a0.x;
            st[i0] = b0;
            st[i1] = b1;
            __syncthreads();
        }
        int j0 = tid, j1 = tid + 512;
#pragma unroll
        for (int q = 9; q >= 0; q--) {
            const int cbit = 9 - q;
            const int tbit = 9 - ((q + 1) % 10);
            j0 ^= ((j0 >> cbit) & 1) << tbit;
            j1 ^= ((j1 >> cbit) & 1) << tbit;
        }
        const float2 r0 = st[j0];
        const float2 r1 = st[j1];
        __syncthreads();
        st[tid]       = r0;
        st[tid + 512] = r1;
        __syncthreads();
    }

    const float2 v0 = st[tid];
    const float2 v1 = st[tid + 512];
    g_probs16[row * QDIM + tid]       = __float2half_rn(v0.x * v0.x + v0.y * v0.y);
    g_probs16[row * QDIM + tid + 512] = __float2half_rn(v1.x * v1.x + v1.y * v1.y);
}

// ---------------------------------------------------------------------------
// K3 v3: out = probs(4096x1024) @ g_wt^T + proj_b   (f16 x f16 -> f32)
// CTA 128x128x32, 8 warps (2x4), warp tile 64x32 -> 64 KB smem, <=128 regs
// => 2 CTAs/SM (occ 25%). 4-stage cp.async, ldmatrix.x4, XOR swizzle.
// ---------------------------------------------------------------------------
#define BM 128
#define BN 128
#define BK 32            // halves
#define STAGES 4
#define A_STG 8192       // 128*32*2 bytes
#define B_STG 8192
#define B_BASE (STAGES * A_STG)
#define K3_SMEM (STAGES * (A_STG + B_STG))   // 64 KB

__device__ __forceinline__ uint32_t smem_u32(const void* p) {
    uint32_t a;
    asm("{ .reg .u64 t; cvta.to.shared.u64 t, %1; cvt.u32.u64 %0, t; }"
        : "=r"(a) : "l"(p));
    return a;
}
__device__ __forceinline__ void cp16(uint32_t saddr, const void* gptr) {
    asm volatile("cp.async.cg.shared.global [%0], [%1], 16;"
                 :: "r"(saddr), "l"(gptr));
}
// swizzled byte offset within a tile for (row r, 16B-chunk kc), rows folded 2/line
__device__ __forceinline__ uint32_t swz(int r, int kc) {
    const int line = r >> 1;
    const int c    = ((r & 1) << 2) + kc;
    return (uint32_t)(line * 128 + ((c ^ (line & 7)) << 4));
}

__global__ __launch_bounds__(256, 2)
void k3_proj_f16v3(const float* __restrict__ pb,
                   float* __restrict__ out) {
    extern __shared__ char smem[];
    const uint32_t sA = smem_u32(smem);
    const uint32_t sB = sA + B_BASE;

    const int tid  = threadIdx.x;
    const int w    = tid >> 5;
    const int lane = tid & 31;
    const int g    = lane >> 2;
    const int tig  = lane & 3;

    const int row0 = blockIdx.x * BM;      // 32 row tiles (fast dim)
    const int col0 = blockIdx.y * BN;      // 239 col tiles

    const int warp_m = (w & 1) * 64;
    const int warp_n = (w >> 1) * 32;

    const __half* Agbase = g_probs16 + (size_t)row0 * QDIM;
    const __half* Bgbase = g_wt      + (size_t)col0 * QDIM;

    // consumer ldmatrix base addresses (stage 0, ks 0)
    const int l16 = lane & 15;
    const int khf = lane >> 4;
    const uint32_t aLM = sA + swz(warp_m + l16, khf);
    const uint32_t bLM = sB + swz(warp_n + l16, khf);

    float acc[4][4][4];
#pragma unroll
    for (int i = 0; i < 4; i++)
#pragma unroll
        for (int j = 0; j < 4; j++)
#pragma unroll
            for (int c = 0; c < 4; c++) acc[i][j][c] = 0.f;

    const int KB = QDIM / BK;   // 32

    // producer mapping: A 512 chunks (2/thread), B 512 chunks (2/thread)
    // prologue: fill stages 0..STAGES-2
#pragma unroll
    for (int s = 0; s < STAGES - 1; s++) {
        const int k0 = s * BK;
#pragma unroll
        for (int j = 0; j < 2; j++) {
            const int i = tid + j * 256;
            const int r = i >> 2, kc = i & 3;
            cp16(sA + s * A_STG + swz(r, kc),
                 Agbase + (size_t)r * QDIM + k0 + kc * 8);
            cp16(sB + s * B_STG + swz(r, kc),
                 Bgbase + (size_t)r * QDIM + k0 + kc * 8);
        }
        asm volatile("cp.async.commit_group;");
    }

    for (int kb = 0; kb < KB; kb++) {
        asm volatile("cp.async.wait_group %0;" :: "n"(STAGES - 2));
        __syncthreads();

        // issue loads for k-block kb+STAGES-1
        {
            const int kn = kb + STAGES - 1;
            if (kn < KB) {
                const int s  = kn & (STAGES - 1);
                const int k0 = kn * BK;
#pragma unroll
                for (int j = 0; j < 2; j++) {
                    const int i = tid + j * 256;
                    const int r = i >> 2, kc = i & 3;
                    cp16(sA + s * A_STG + swz(r, kc),
                         Agbase + (size_t)r * QDIM + k0 + kc * 8);
                    cp16(sB + s * B_STG + swz(r, kc),
                         Bgbase + (size_t)r * QDIM + k0 + kc * 8);
                }
            }
            asm volatile("cp.async.commit_group;");
        }

        // compute on stage kb%STAGES
        const int s = kb & (STAGES - 1);
        const uint32_t aS = aLM + s * A_STG;
        const uint32_t bS = bLM + s * B_STG;
#pragma unroll
        for (int ks = 0; ks < 2; ks++) {
            const uint32_t kx = ks * 32;    // toggle chunk bit1 (16 halves)
            uint32_t af[4][4];
#pragma unroll
            for (int mt = 0; mt < 4; mt++) {
                asm volatile(
                    "ldmatrix.sync.aligned.m8n8.x4.shared.b16 {%0,%1,%2,%3}, [%4];"
                    : "=r"(af[mt][0]), "=r"(af[mt][1]),
                      "=r"(af[mt][2]), "=r"(af[mt][3])
                    : "r"((aS + mt * 1024) ^ kx));
            }
            uint32_t bf[4][2];
#pragma unroll
            for (int ntp = 0; ntp < 2; ntp++) {
                uint32_t r0, r1, r2, r3;
                asm volatile(
                    "ldmatrix.sync.aligned.m8n8.x4.shared.b16 {%0,%1,%2,%3}, [%4];"
                    : "=r"(r0), "=r"(r1), "=r"(r2), "=r"(r3)
                    : "r"((bS + ntp * 1024) ^ kx));
                bf[2*ntp][0]   = r0; bf[2*ntp][1]   = r2;
                bf[2*ntp+1][0] = r1; bf[2*ntp+1][1] = r3;
            }
#pragma unroll
            for (int mt = 0; mt < 4; mt++)
#pragma unroll
                for (int nt = 0; nt < 4; nt++) {
                    asm volatile(
                        "mma.sync.aligned.m16n8k16.row.col.f32.f16.f16.f32 "
                        "{%0,%1,%2,%3}, {%4,%5,%6,%7}, {%8,%9}, {%0,%1,%2,%3};"
                        : "+f"(acc[mt][nt][0]), "+f"(acc[mt][nt][1]),
                          "+f"(acc[mt][nt][2]), "+f"(acc[mt][nt][3])
                        : "r"(af[mt][0]), "r"(af[mt][1]),
                          "r"(af[mt][2]), "r"(af[mt][3]),
                          "r"(bf[nt][0]), "r"(bf[nt][1]));
                }
        }
    }

    // ---- epilogue ----
#pragma unroll
    for (int mt = 0; mt < 4; mt++) {
#pragma unroll
        for (int nt = 0; nt < 4; nt++) {
            const int row = row0 + warp_m + mt * 16 + g;
            const int col = col0 + warp_n + nt * 8 + tig * 2;
            if (col < VOCAB) {   // VOCAB even -> pair never straddles
                const float b0 = pb[col], b1 = pb[col + 1];
                float2 v0 = make_float2(acc[mt][nt][0] + b0, acc[mt][nt][1] + b1);
                float2 v1 = make_float2(acc[mt][nt][2] + b0, acc[mt][nt][3] + b1);
                __stcs((float2*)(out + (size_t)row * VOCAB + col), v0);
                __stcs((float2*)(out + (size_t)(row + 8) * VOCAB + col), v1);
            }
        }
    }
}

// ---------------------------------------------------------------------------
extern "C" void kernel_launch(void* const* d_in, const int* in_sizes, int n_in,
                              void* d_out, int out_size) {
    const float* x    = (const float*)d_in[0];
    const float* W    = (const float*)d_in[1];
    const float* db   = (const float*)d_in[2];
    const float* lnw  = (const float*)d_in[3];
    const float* lnb  = (const float*)d_in[4];
    const float* entw = (const float*)d_in[5];
    const float* entb = (const float*)d_in[6];
    const float* pw   = (const float*)d_in[7];
    const float* pb   = (const float*)d_in[8];
    float* out = (float*)d_out;

    dim3 gT(VPAD / 32, QDIM / 32);
    kT_transpose<<<gT, 256>>>(pw);
    k1_dense_ln_ang<<<M_ROWS / 8, 256>>>(x, W, db, lnw, lnb, entw, entb);
    k2_quantum<<<M_ROWS, 512>>>();

    cudaFuncSetAttribute(k3_proj_f16v3,
                         cudaFuncAttributeMaxDynamicSharedMemorySize, K3_SMEM);
    dim3 g3(M_ROWS / BM, VPAD / BN);    // (32, 239), row tiles fastest
    k3_proj_f16v3<<<g3, 256, K3_SMEM>>>(pb, out);
}